// round 12
// baseline (speedup 1.0000x reference)
#include <cuda_runtime.h>
#include <cuda_fp16.h>
#include <math.h>
#include <cstdint>

#define B_ 64
#define L_ 2048
#define H_ 1024
#define U_ 1024
#define E_ 256
#define V_ 32000

// Scratch (no allocations allowed -> __device__ globals)
__device__ float g_scores[B_ * L_];
__device__ float g_hidt[B_ * U_];
__device__ float g_context[B_ * U_];
__device__ __half g_w1t16[1024 * 1024];             // w1^T (n,k) fp16

// ===========================================================================
// Helpers
// ===========================================================================
__device__ __forceinline__ uint32_t smem_u32(const void* p) {
    uint32_t a;
    asm("{ .reg .u64 t; cvta.to.shared.u64 t, %1; cvt.u32.u64 %0, t; }" : "=r"(a) : "l"(p));
    return a;
}
#define CP_ASYNC16(dst, src) \
    asm volatile("cp.async.cg.shared.global [%0], [%1], 16;" :: "r"(dst), "l"(src) : "memory")
#define CP_COMMIT() asm volatile("cp.async.commit_group;" ::: "memory")
#define CP_WAIT0()  asm volatile("cp.async.wait_group 0;" ::: "memory")
#define CP_WAIT1()  asm volatile("cp.async.wait_group 1;" ::: "memory")
#define LDM4(r, addr)                                                               \
    asm volatile("ldmatrix.sync.aligned.m8n8.x4.shared.b16 {%0,%1,%2,%3}, [%4];"    \
                 : "=r"((r)[0]), "=r"((r)[1]), "=r"((r)[2]), "=r"((r)[3]) : "r"(addr))

__device__ __forceinline__ void mma_f16(float* c, const uint32_t* a, uint32_t b0, uint32_t b1) {
    asm volatile(
        "mma.sync.aligned.m16n8k16.row.col.f32.f16.f16.f32 "
        "{%0,%1,%2,%3}, {%4,%5,%6,%7}, {%8,%9}, {%0,%1,%2,%3};"
        : "+f"(c[0]), "+f"(c[1]), "+f"(c[2]), "+f"(c[3])
        : "r"(a[0]), "r"(a[1]), "r"(a[2]), "r"(a[3]), "r"(b0), "r"(b1));
}
__device__ __forceinline__ float fast_tanh(float x) {
    float r; asm("tanh.approx.f32 %0, %1;" : "=f"(r) : "f"(x)); return r;
}

// ===========================================================================
// zero_seed: g_scores = 0; g_hidt = b1+b2 (pre-seed); g_context = 0.
// grid 512, block 256.
// ===========================================================================
__global__ void zero_seed(const float* __restrict__ b1, const float* __restrict__ b2) {
    int j = blockIdx.x * 256 + threadIdx.x;
    g_scores[j] = 0.f;
    if (blockIdx.x < 256) g_hidt[j] = b1[j & 1023] + b2[j & 1023];
    else                  g_context[j - 65536] = 0.f;
}

// ===========================================================================
// w1 (K=1024, N=1024) row-major -> g_w1t16 (N, K) K-major fp16
// ===========================================================================
__global__ void transpose_w1h(const float* __restrict__ w1) {
    __shared__ float t[32][33];
    int bx = blockIdx.x * 32, by = blockIdx.y * 32;
    int x = threadIdx.x, y = threadIdx.y;
#pragma unroll
    for (int i = 0; i < 32; i += 8) t[y + i][x] = w1[(size_t)(by + y + i) * 1024 + bx + x];
    __syncthreads();
#pragma unroll
    for (int i = 0; i < 32; i += 8)
        g_w1t16[(size_t)(bx + y + i) * 1024 + by + x] = __float2half_rn(t[x][y + i]);
}

// ===========================================================================
// hid_t partial GEMM, k-split (R7-measured: 35.7 us):
// g_hidt[m,n] += hidden[m, k0:k0+256] @ w2 slab.  grid (64, 4), block 256.
// ===========================================================================
__global__ void hidt_kernel(const float* __restrict__ hidden, const float* __restrict__ w2) {
    __shared__ float hs[256];
    int tid = threadIdx.x;
    int m = blockIdx.x;
    int k0 = blockIdx.y * 256;
    hs[tid] = hidden[m * 1024 + k0 + tid];
    __syncthreads();
    const float4* w2q = (const float4*)(w2 + (size_t)k0 * 1024) + tid;
    float4 acc = make_float4(0.f, 0.f, 0.f, 0.f);
#pragma unroll 8
    for (int k = 0; k < 256; k++) {
        float4 w = w2q[(size_t)k * 256];
        float h = hs[k];
        acc.x += h * w.x; acc.y += h * w.y; acc.z += h * w.z; acc.w += h * w.w;
    }
    float* d = g_hidt + m * 1024 + tid * 4;
    atomicAdd(d + 0, acc.x);
    atomicAdd(d + 1, acc.y);
    atomicAdd(d + 2, acc.z);
    atomicAdd(d + 3, acc.w);
}

// ===========================================================================
// Fused attention-score GEMM, fp16 HMMA + ldmatrix.
//   A: enc fp32 read DIRECTLY (no convert pass), cvt to fp16 in registers,
//      staged ONE iteration ahead (LDG at kt -> STS at kt+1) so global
//      latency hides behind a full compute phase.
//   B: w1^T fp16 via 3-stage cp.async ring.
//   CTA tile 128x128, K=1024 in 16 tiles of 64. Warp grid 2(M)x4(N).
//   Epilogue: score[row] += sum_col tanh(acc + hidt)*vw; smem rowsum;
//   1 global atomic per row per CTA.  grid (8 colTiles, 1024 rowTiles).
// ===========================================================================
#define ST_BYTES 36864            // stage: A 128*144 + B 128*144
#define BT_OFF   18432
#define EX_OFF   (3 * ST_BYTES)
#define SC_SMEM  (EX_OFF + 3 * 128 * 4)

__global__ __launch_bounds__(256)
void score_fp16(const float* __restrict__ enc, const float* __restrict__ vw) {
    extern __shared__ char smc[];
    float* cb  = (float*)(smc + EX_OFF);
    float* vws = cb + 128;
    float* rs  = vws + 128;
    const uint32_t sb = smem_u32(smc);
    const int tid = threadIdx.x;
    const int row0 = blockIdx.y * 128;
    const int col0 = blockIdx.x * 128;
    const int b = blockIdx.y >> 4;

    if (tid < 128) {
        cb[tid]  = g_hidt[b * 1024 + col0 + tid];
        vws[tid] = vw[col0 + tid];
        rs[tid]  = 0.f;
    }

    const float* gA = enc + (size_t)row0 * 1024;

    // ---- A: LDG fp32 -> cvt -> regs (16 uint32), then STS next iter ----
    uint2 aregs[8];
#define LDG_CVT(kt) do {                                                            \
        _Pragma("unroll")                                                           \
        for (int q = 0; q < 8; q++) {                                               \
            int id = tid + q * 256;                                                 \
            int r = id >> 4, c = id & 15;                                           \
            float4 v = *(const float4*)(gA + (size_t)r * 1024 + (kt) * 64 + c * 4); \
            __half2 h0 = __floats2half2_rn(v.x, v.y);                               \
            __half2 h1 = __floats2half2_rn(v.z, v.w);                               \
            aregs[q].x = *(uint32_t*)&h0;                                           \
            aregs[q].y = *(uint32_t*)&h1;                                           \
        }                                                                           \
    } while (0)
#define STS_A(kt) do {                                                              \
        char* so = smc + ((kt) % 3) * ST_BYTES;                                     \
        _Pragma("unroll")                                                           \
        for (int q = 0; q < 8; q++) {                                               \
            int id = tid + q * 256;                                                 \
            int r = id >> 4, c = id & 15;                                           \
            *(uint2*)(so + r * 144 + c * 8) = aregs[q];                             \
        }                                                                           \
    } while (0)
#define LOAD_B(kt) do {                                                             \
        const uint32_t so = sb + ((kt) % 3) * ST_BYTES;                             \
        _Pragma("unroll")                                                           \
        for (int q = 0; q < 4; q++) {                                               \
            int c = tid + q * 256;                                                  \
            int r = c >> 3, cc = c & 7;                                             \
            CP_ASYNC16(so + BT_OFF + r * 144 + cc * 16,                             \
                       g_w1t16 + (size_t)(col0 + r) * 1024 + (kt) * 64 + cc * 8);   \
        }                                                                           \
        CP_COMMIT();                                                                \
    } while (0)

    const int lane = tid & 31, warp = tid >> 5;
    const int wm = warp >> 2, wn = warp & 3;   // 2 x 4 warp grid
    const int g = lane >> 2, t = lane & 3;

    const int aRow = wm * 64 + (lane & 7) + ((lane >> 3) & 1) * 8;
    const int aCol = ((lane >> 4) & 1) * 8;
    const int bRow = wn * 32 + (lane & 7) + ((lane >> 4) & 1) * 8;
    const int bCol = ((lane >> 3) & 1) * 8;
    const uint32_t aBase = sb + aRow * 144 + aCol * 2;
    const uint32_t bBase = sb + BT_OFF + bRow * 144 + bCol * 2;

    float c[4][4][4] = {};

    // Prologue: A(0) to smem; B(0), B(1) in flight; A(1) staged in regs.
    LDG_CVT(0);
    STS_A(0);
    LOAD_B(0);
    LOAD_B(1);
    LDG_CVT(1);
    __syncthreads();                 // publish A(0)

    for (int kt = 0; kt < 16; kt++) {
        if (kt < 15) CP_WAIT1(); else CP_WAIT0();   // B(kt) arrived
        __syncthreads();             // B(kt)+A(kt) visible; stages (kt±) free per ring proof
        if (kt + 1 < 16) STS_A(kt + 1);             // from aregs (loaded last iter)
        if (kt + 2 < 16) { LOAD_B(kt + 2); LDG_CVT(kt + 2); }

        const uint32_t so = ((uint32_t)(kt % 3)) * ST_BYTES;
#pragma unroll
        for (int ks = 0; ks < 4; ks++) {
            uint32_t a[4][4], bb[2][4];
#pragma unroll
            for (int ma = 0; ma < 4; ma++)
                LDM4(a[ma], aBase + so + ma * (16 * 144) + ks * 32);
#pragma unroll
            for (int pr = 0; pr < 2; pr++)
                LDM4(bb[pr], bBase + so + pr * (16 * 144) + ks * 32);
#pragma unroll
            for (int ma = 0; ma < 4; ma++)
#pragma unroll
                for (int na = 0; na < 4; na++)
                    mma_f16(c[ma][na], a[ma], bb[na >> 1][(na & 1) * 2],
                            bb[na >> 1][(na & 1) * 2 + 1]);
        }
    }

    // Epilogue: p[row] = sum over this warp's 32 cols of tanh(acc+cb)*vw
#pragma unroll
    for (int ma = 0; ma < 4; ma++) {
        float p0 = 0.f, p1 = 0.f;
#pragma unroll
        for (int na = 0; na < 4; na++) {
            int col = wn * 32 + na * 8 + 2 * t;
            float cb0 = cb[col], cb1 = cb[col + 1];
            float v0 = vws[col], v1 = vws[col + 1];
            p0 += fast_tanh(c[ma][na][0] + cb0) * v0 + fast_tanh(c[ma][na][1] + cb1) * v1;
            p1 += fast_tanh(c[ma][na][2] + cb0) * v0 + fast_tanh(c[ma][na][3] + cb1) * v1;
        }
        p0 += __shfl_xor_sync(0xffffffffu, p0, 1);
        p0 += __shfl_xor_sync(0xffffffffu, p0, 2);
        p1 += __shfl_xor_sync(0xffffffffu, p1, 1);
        p1 += __shfl_xor_sync(0xffffffffu, p1, 2);
        if (t == 0) {
            atomicAdd(&rs[wm * 64 + ma * 16 + g], p0);
            atomicAdd(&rs[wm * 64 + ma * 16 + g + 8], p1);
        }
    }
    __syncthreads();
    if (tid < 128) atomicAdd(&g_scores[row0 + tid], rs[tid]);
#undef LDG_CVT
#undef STS_A
#undef LOAD_B
}

// ===========================================================================
// Softmax over L=2048 per batch; writes attention weights straight to output.
// ===========================================================================
__global__ void softmax_kernel(float* __restrict__ attn) {
    __shared__ float red[256];
    int b = blockIdx.x, tid = threadIdx.x;
    float v[8];
    float mx = -1e30f;
#pragma unroll
    for (int i = 0; i < 8; i++) {
        v[i] = g_scores[b * 2048 + i * 256 + tid];
        mx = fmaxf(mx, v[i]);
    }
    red[tid] = mx;
    __syncthreads();
    for (int s = 128; s > 0; s >>= 1) {
        if (tid < s) red[tid] = fmaxf(red[tid], red[tid + s]);
        __syncthreads();
    }
    mx = red[0];
    __syncthreads();
    float sum = 0.f;
#pragma unroll
    for (int i = 0; i < 8; i++) {
        v[i] = expf(v[i] - mx);
        sum += v[i];
    }
    red[tid] = sum;
    __syncthreads();
    for (int s = 128; s > 0; s >>= 1) {
        if (tid < s) red[tid] += red[tid + s];
        __syncthreads();
    }
    float inv = 1.f / red[0];
#pragma unroll
    for (int i = 0; i < 8; i++) attn[b * 2048 + i * 256 + tid] = v[i] * inv;
}

// ===========================================================================
// context[b,u] = sum_l attn[b,l]*enc[b,l,u] — fp32 enc (R5-measured pattern).
// grid (64 b, 8 l-splits), block 256.
// ===========================================================================
__global__ void context_kernel(const float* __restrict__ enc, const float* __restrict__ attn) {
    __shared__ float aw[256];
    int tid = threadIdx.x;
    int b = blockIdx.x;
    int l0 = blockIdx.y * 256;
    aw[tid] = attn[b * 2048 + l0 + tid];
    __syncthreads();
    const float4* p = (const float4*)(enc + ((size_t)b * 2048 + l0) * 1024) + tid;
    float4 acc = make_float4(0.f, 0.f, 0.f, 0.f);
#pragma unroll 4
    for (int l = 0; l < 256; l++) {
        float4 v = p[(size_t)l * 256];
        float w = aw[l];
        acc.x += w * v.x; acc.y += w * v.y; acc.z += w * v.z; acc.w += w * v.w;
    }
    float* c = g_context + b * 1024 + tid * 4;
    atomicAdd(c + 0, acc.x);
    atomicAdd(c + 1, acc.y);
    atomicAdd(c + 2, acc.z);
    atomicAdd(c + 3, acc.w);
}

// ===========================================================================
// GRU step, h0 = 0: z = sigmoid(zi_z); state = (1-z)*tanh(zi_h).
// r and gru_rk are dead (h0 @ gru_rk == 0). xin = [context | emb[x]].
// ===========================================================================
__global__ void gru_kernel(const float* __restrict__ emb, const int* __restrict__ x,
                           const float* __restrict__ gru_k, const float* __restrict__ gru_b,
                           float* __restrict__ state) {
    __shared__ float xs[2][1280];
    int tid = threadIdx.x;
    int n = blockIdx.x * 128 + (tid & 127);
    int mi = tid >> 7;
    int m = blockIdx.y * 2 + mi;
    for (int i = tid; i < 2 * 1280; i += 256) {
        int mm = i / 1280, k = i % 1280;
        int gm = blockIdx.y * 2 + mm;
        xs[mm][k] = (k < 1024) ? g_context[gm * 1024 + k]
                               : emb[(size_t)x[gm] * 256 + (k - 1024)];
    }
    __syncthreads();
    float az = 0.f, ah = 0.f;
#pragma unroll 4
    for (int k = 0; k < 1280; k++) {
        float xv = xs[mi][k];
        az += xv * gru_k[(size_t)k * 3072 + n];
        ah += xv * gru_k[(size_t)k * 3072 + 2048 + n];
    }
    float z = 1.f / (1.f + expf(-(az + gru_b[n])));
    float hh = tanhf(ah + gru_b[2048 + n]);
    state[m * 1024 + n] = (1.f - z) * hh;
}

// ===========================================================================
// logits = state @ out_w + out_b   (M=64, N=32000, K=1024) — fp32 SIMT
// ===========================================================================
__global__ __launch_bounds__(256)
void logits_kernel(const float* __restrict__ state, const float* __restrict__ out_w,
                   const float* __restrict__ out_b, float* __restrict__ logits) {
    __shared__ float ss[64][64];
    int tid = threadIdx.x;
    int n = blockIdx.x * 128 + (tid & 31) * 4;
    int mg = tid >> 5;
    float acc[8][4] = {};
    for (int kt = 0; kt < 1024; kt += 64) {
        __syncthreads();
        for (int f = tid; f < 1024; f += 256) {
            int mm = f >> 4, kq = (f & 15) << 2;
            *(float4*)&ss[mm][kq] = *(const float4*)(state + mm * 1024 + kt + kq);
        }
        __syncthreads();
#pragma unroll 8
        for (int k = 0; k < 64; k++) {
            float4 w = *(const float4*)(out_w + (size_t)(kt + k) * 32000 + n);
#pragma unroll
            for (int mm = 0; mm < 8; mm++) {
                float s = ss[mg * 8 + mm][k];
                acc[mm][0] += s * w.x;
                acc[mm][1] += s * w.y;
                acc[mm][2] += s * w.z;
                acc[mm][3] += s * w.w;
            }
        }
    }
    float4 bv = *(const float4*)(out_b + n);
#pragma unroll
    for (int mm = 0; mm < 8; mm++) {
        float4 o;
        o.x = acc[mm][0] + bv.x;
        o.y = acc[mm][1] + bv.y;
        o.z = acc[mm][2] + bv.z;
        o.w = acc[mm][3] + bv.w;
        *(float4*)(logits + (size_t)(mg * 8 + mm) * 32000 + n) = o;
    }
}

// ===========================================================================
extern "C" void kernel_launch(void* const* d_in, const int* in_sizes, int n_in,
                              void* d_out, int out_size) {
    const int*   x      = (const int*)  d_in[0];
    const float* hidden = (const float*)d_in[1];
    const float* enc    = (const float*)d_in[2];
    const float* emb    = (const float*)d_in[3];
    const float* w1     = (const float*)d_in[4];
    const float* b1     = (const float*)d_in[5];
    const float* w2     = (const float*)d_in[6];
    const float* b2     = (const float*)d_in[7];
    const float* v_w    = (const float*)d_in[8];
    // d_in[9]  = v_b   : softmax-invariant uniform shift -> unused
    const float* gru_k  = (const float*)d_in[10];
    // d_in[11] = gru_rk: multiplied by h0 == 0 -> unused
    const float* gru_b  = (const float*)d_in[12];
    const float* out_w  = (const float*)d_in[13];
    const float* out_b  = (const float*)d_in[14];

    float* out    = (float*)d_out;
    float* logits = out;                          // (64, 32000)
    float* state  = out + (size_t)B_ * V_;        // (64, 1024)
    float* attn   = state + (size_t)B_ * U_;      // (64, 2048)

    cudaFuncSetAttribute(score_fp16, cudaFuncAttributeMaxDynamicSharedMemorySize, SC_SMEM);

    zero_seed<<<512, 256>>>(b1, b2);
    transpose_w1h<<<dim3(32, 32), dim3(32, 8)>>>(w1);
    hidt_kernel<<<dim3(64, 4), 256>>>(hidden, w2);
    score_fp16<<<dim3(8, 1024), 256, SC_SMEM>>>(enc, v_w);   // launch #4 (profiled)
    softmax_kernel<<<64, 256>>>(attn);
    context_kernel<<<dim3(64, 8), 256>>>(enc, attn);
    gru_kernel<<<dim3(8, 32), 256>>>(emb, x, gru_k, gru_b, state);
    logits_kernel<<<250, 256>>>(state, out_w, out_b, logits);
}

// round 16
// speedup vs baseline: 1.1111x; 1.1111x over previous
#include <cuda_runtime.h>
#include <cuda_fp16.h>
#include <math.h>
#include <cstdint>

#define B_ 64
#define L_ 2048
#define H_ 1024
#define U_ 1024
#define E_ 256
#define V_ 32000

// Scratch (no allocations allowed -> __device__ globals)
__device__ float g_scores[B_ * L_];
__device__ float g_hidt[B_ * U_];
__device__ float g_context[B_ * U_];
__device__ __half g_enc16[(size_t)B_ * L_ * H_];   // enc converted to fp16
__device__ __half g_w1t16[1024 * 1024];            // w1^T (n,k) fp16

// ===========================================================================
// Helpers
// ===========================================================================
__device__ __forceinline__ uint32_t smem_u32(const void* p) {
    uint32_t a;
    asm("{ .reg .u64 t; cvta.to.shared.u64 t, %1; cvt.u32.u64 %0, t; }" : "=r"(a) : "l"(p));
    return a;
}
#define CP_ASYNC16(dst, src) \
    asm volatile("cp.async.cg.shared.global [%0], [%1], 16;" :: "r"(dst), "l"(src) : "memory")
#define CP_COMMIT() asm volatile("cp.async.commit_group;" ::: "memory")
#define CP_WAIT0()  asm volatile("cp.async.wait_group 0;" ::: "memory")
#define LDM4(r, addr)                                                               \
    asm volatile("ldmatrix.sync.aligned.m8n8.x4.shared.b16 {%0,%1,%2,%3}, [%4];"    \
                 : "=r"((r)[0]), "=r"((r)[1]), "=r"((r)[2]), "=r"((r)[3]) : "r"(addr))

__device__ __forceinline__ void mma_f16(float* c, const uint32_t* a, uint32_t b0, uint32_t b1) {
    asm volatile(
        "mma.sync.aligned.m16n8k16.row.col.f32.f16.f16.f32 "
        "{%0,%1,%2,%3}, {%4,%5,%6,%7}, {%8,%9}, {%0,%1,%2,%3};"
        : "+f"(c[0]), "+f"(c[1]), "+f"(c[2]), "+f"(c[3])
        : "r"(a[0]), "r"(a[1]), "r"(a[2]), "r"(a[3]), "r"(b0), "r"(b1));
}
__device__ __forceinline__ float fast_tanh(float x) {
    float r; asm("tanh.approx.f32 %0, %1;" : "=f"(r) : "f"(x)); return r;
}

// ===========================================================================
// Init scratch: scores/context = 0, hidt = b1 + b2 (bias pre-seed for atomics)
// ===========================================================================
__global__ void zero_kernel(const float* __restrict__ b1, const float* __restrict__ b2) {
    int i = blockIdx.x * blockDim.x + threadIdx.x;
    if (i < B_ * L_) g_scores[i] = 0.f;
    if (i < B_ * U_) {
        g_context[i] = 0.f;
        int n = i & 1023;
        g_hidt[i] = b1[n] + b2[n];
    }
}

// ===========================================================================
// enc fp32 -> fp16, 8 elements per thread (16B stores)
// ===========================================================================
__global__ void convert_enc(const float* __restrict__ enc) {
    size_t i = ((size_t)blockIdx.x * 256 + threadIdx.x) * 8;
    if (i + 7 >= (size_t)B_ * L_ * H_) return;
    float4 v0 = *(const float4*)(enc + i);
    float4 v1 = *(const float4*)(enc + i + 4);
    __half2 h0 = __floats2half2_rn(v0.x, v0.y);
    __half2 h1 = __floats2half2_rn(v0.z, v0.w);
    __half2 h2 = __floats2half2_rn(v1.x, v1.y);
    __half2 h3 = __floats2half2_rn(v1.z, v1.w);
    uint4 o;
    o.x = *(uint32_t*)&h0; o.y = *(uint32_t*)&h1;
    o.z = *(uint32_t*)&h2; o.w = *(uint32_t*)&h3;
    *(uint4*)(g_enc16 + i) = o;
}

// ===========================================================================
// w1 (K=1024, N=1024) row-major -> g_w1t16 (N, K) K-major fp16
// ===========================================================================
__global__ void transpose_w1h(const float* __restrict__ w1) {
    __shared__ float t[32][33];
    int bx = blockIdx.x * 32, by = blockIdx.y * 32;
    int x = threadIdx.x, y = threadIdx.y;
#pragma unroll
    for (int i = 0; i < 32; i += 8) t[y + i][x] = w1[(size_t)(by + y + i) * 1024 + bx + x];
    __syncthreads();
#pragma unroll
    for (int i = 0; i < 32; i += 8)
        g_w1t16[(size_t)(bx + y + i) * 1024 + by + x] = __float2half_rn(t[x][y + i]);
}

// ===========================================================================
// hid_t partial GEMM, k-split: g_hidt[m,n] += hidden[m, k0:k0+256] @ w2 slab.
// grid (64 m, 4 k-splits), 256 threads: thread t owns n-quad [4t, 4t+4).
// (R7-measured: 35.7 us)
// ===========================================================================
__global__ void hidt_kernel(const float* __restrict__ hidden, const float* __restrict__ w2) {
    __shared__ float hs[256];
    int tid = threadIdx.x;
    int m = blockIdx.x;
    int k0 = blockIdx.y * 256;
    hs[tid] = hidden[m * 1024 + k0 + tid];
    __syncthreads();
    const float4* w2q = (const float4*)(w2 + (size_t)k0 * 1024) + tid;
    float4 acc = make_float4(0.f, 0.f, 0.f, 0.f);
#pragma unroll 8
    for (int k = 0; k < 256; k++) {
        float4 w = w2q[(size_t)k * 256];
        float h = hs[k];
        acc.x += h * w.x; acc.y += h * w.y; acc.z += h * w.z; acc.w += h * w.w;
    }
    float* d = g_hidt + m * 1024 + tid * 4;
    atomicAdd(d + 0, acc.x);
    atomicAdd(d + 1, acc.y);
    atomicAdd(d + 2, acc.z);
    atomicAdd(d + 3, acc.w);
}

// ===========================================================================
// Fused attention-score GEMM, fp16 HMMA + ldmatrix + 2-stage cp.async.
//   (byte-identical to the round-7 best-measured kernel: 755.6 us)
// ===========================================================================
#define ST_BYTES 36864            // one stage: (128 A + 128 B rows) * 144 B
#define BT_OFF   18432            // B region offset inside a stage
#define EX_OFF   (2 * ST_BYTES)   // extras after 2 stages
#define SC_SMEM  (EX_OFF + 3 * 128 * 4)

__global__ __launch_bounds__(256, 2)
void score_fp16(const float* __restrict__ vw) {
    extern __shared__ char smc[];
    float* cb  = (float*)(smc + EX_OFF);
    float* vws = cb + 128;
    float* rs  = vws + 128;
    const uint32_t sb = smem_u32(smc);
    const int tid = threadIdx.x;
    const int row0 = blockIdx.y * 128;
    const int col0 = blockIdx.x * 128;
    const int b = blockIdx.y >> 4;

    if (tid < 128) {
        cb[tid]  = g_hidt[b * 1024 + col0 + tid];
        vws[tid] = vw[col0 + tid];
        rs[tid]  = 0.f;
    }

    const __half* gA = g_enc16 + (size_t)row0 * 1024;
    const __half* gB = g_w1t16 + (size_t)col0 * 1024;

#define LOAD_TILE(kt) do {                                                          \
        const uint32_t so = sb + ((kt) & 1) * ST_BYTES;                             \
        _Pragma("unroll")                                                           \
        for (int q = 0; q < 4; q++) {                                               \
            int c = tid + q * 256;                                                  \
            int r = c >> 3, cc = c & 7;                                             \
            CP_ASYNC16(so + r * 144 + cc * 16,                                      \
                       gA + (size_t)r * 1024 + (kt) * 64 + cc * 8);                 \
            CP_ASYNC16(so + BT_OFF + r * 144 + cc * 16,                             \
                       gB + (size_t)r * 1024 + (kt) * 64 + cc * 8);                 \
        }                                                                           \
        CP_COMMIT();                                                                \
    } while (0)

    const int lane = tid & 31, warp = tid >> 5;
    const int wm = warp >> 2, wn = warp & 3;   // 2 x 4 warp grid
    const int g = lane >> 2, t = lane & 3;

    const int aRow = wm * 64 + (lane & 7) + ((lane >> 3) & 1) * 8;
    const int aCol = ((lane >> 4) & 1) * 8;
    const int bRow = wn * 32 + (lane & 7) + ((lane >> 4) & 1) * 8;
    const int bCol = ((lane >> 3) & 1) * 8;
    const uint32_t aBase = sb + aRow * 144 + aCol * 2;
    const uint32_t bBase = sb + BT_OFF + bRow * 144 + bCol * 2;

    float c[4][4][4] = {};

    LOAD_TILE(0);

    for (int kt = 0; kt < 16; kt++) {
        CP_WAIT0();                 // stage kt ready
        __syncthreads();            // everyone done with stage kt-1 buffer
        if (kt + 1 < 16) LOAD_TILE(kt + 1);   // fill other stage, overlaps compute

        const uint32_t so = ((uint32_t)(kt & 1)) * ST_BYTES;
#pragma unroll
        for (int ks = 0; ks < 4; ks++) {
            uint32_t a[4][4], bb[2][4];
#pragma unroll
            for (int ma = 0; ma < 4; ma++)
                LDM4(a[ma], aBase + so + ma * (16 * 144) + ks * 32);
#pragma unroll
            for (int pr = 0; pr < 2; pr++)
                LDM4(bb[pr], bBase + so + pr * (16 * 144) + ks * 32);
#pragma unroll
            for (int ma = 0; ma < 4; ma++)
#pragma unroll
                for (int na = 0; na < 4; na++)
                    mma_f16(c[ma][na], a[ma], bb[na >> 1][(na & 1) * 2],
                            bb[na >> 1][(na & 1) * 2 + 1]);
        }
        __syncthreads();            // compute(kt) done before next refill of this stage
    }

    // Epilogue: p[row] = sum over this warp's 32 cols of tanh(acc+cb)*vw
#pragma unroll
    for (int ma = 0; ma < 4; ma++) {
        float p0 = 0.f, p1 = 0.f;
#pragma unroll
        for (int na = 0; na < 4; na++) {
            int col = wn * 32 + na * 8 + 2 * t;
            float cb0 = cb[col], cb1 = cb[col + 1];
            float v0 = vws[col], v1 = vws[col + 1];
            p0 += fast_tanh(c[ma][na][0] + cb0) * v0 + fast_tanh(c[ma][na][1] + cb1) * v1;
            p1 += fast_tanh(c[ma][na][2] + cb0) * v0 + fast_tanh(c[ma][na][3] + cb1) * v1;
        }
        p0 += __shfl_xor_sync(0xffffffffu, p0, 1);
        p0 += __shfl_xor_sync(0xffffffffu, p0, 2);
        p1 += __shfl_xor_sync(0xffffffffu, p1, 1);
        p1 += __shfl_xor_sync(0xffffffffu, p1, 2);
        if (t == 0) {
            atomicAdd(&rs[wm * 64 + ma * 16 + g], p0);
            atomicAdd(&rs[wm * 64 + ma * 16 + g + 8], p1);
        }
    }
    __syncthreads();
    if (tid < 128) atomicAdd(&g_scores[row0 + tid], rs[tid]);
#undef LOAD_TILE
}

// ===========================================================================
// Softmax over L=2048 per batch; writes attention weights straight to output.
// ===========================================================================
__global__ void softmax_kernel(float* __restrict__ attn) {
    __shared__ float red[256];
    int b = blockIdx.x, tid = threadIdx.x;
    float v[8];
    float mx = -1e30f;
#pragma unroll
    for (int i = 0; i < 8; i++) {
        v[i] = g_scores[b * 2048 + i * 256 + tid];
        mx = fmaxf(mx, v[i]);
    }
    red[tid] = mx;
    __syncthreads();
    for (int s = 128; s > 0; s >>= 1) {
        if (tid < s) red[tid] = fmaxf(red[tid], red[tid + s]);
        __syncthreads();
    }
    mx = red[0];
    __syncthreads();
    float sum = 0.f;
#pragma unroll
    for (int i = 0; i < 8; i++) {
        v[i] = expf(v[i] - mx);
        sum += v[i];
    }
    red[tid] = sum;
    __syncthreads();
    for (int s = 128; s > 0; s >>= 1) {
        if (tid < s) red[tid] += red[tid + s];
        __syncthreads();
    }
    float inv = 1.f / red[0];
#pragma unroll
    for (int i = 0; i < 8; i++) attn[b * 2048 + i * 256 + tid] = v[i] * inv;
}

// ===========================================================================
// context[b,u] = sum_l attn[b,l]*enc16[b,l,u] — fp16 enc, fp32 accumulate.
// v2: grid (64 b, 16 l-splits) = 1024 CTAs (2x parallelism), 128-l chunks,
// unroll 8 -> 8 independent 8B loads in flight per thread (MLP 8).
// ===========================================================================
__global__ void context_kernel(const float* __restrict__ attn) {
    __shared__ float aw[128];
    int tid = threadIdx.x;
    int b = blockIdx.x;
    int l0 = blockIdx.y * 128;
    if (tid < 128) aw[tid] = attn[b * 2048 + l0 + tid];
    __syncthreads();
    const __half* p = g_enc16 + ((size_t)b * 2048 + l0) * 1024 + tid * 4;
    float4 acc = make_float4(0.f, 0.f, 0.f, 0.f);
#pragma unroll 8
    for (int l = 0; l < 128; l++) {
        uint2 raw = *(const uint2*)(p + (size_t)l * 1024);
        __half2 h0 = *(__half2*)&raw.x;
        __half2 h1 = *(__half2*)&raw.y;
        float2 f0 = __half22float2(h0);
        float2 f1 = __half22float2(h1);
        float w = aw[l];
        acc.x += w * f0.x; acc.y += w * f0.y; acc.z += w * f1.x; acc.w += w * f1.y;
    }
    float* c = g_context + b * 1024 + tid * 4;
    atomicAdd(c + 0, acc.x);
    atomicAdd(c + 1, acc.y);
    atomicAdd(c + 2, acc.z);
    atomicAdd(c + 3, acc.w);
}

// ===========================================================================
// GRU step, h0 = 0: z = sigmoid(zi_z); state = (1-z)*tanh(zi_h).
// r and gru_rk are dead (h0 @ gru_rk == 0). xin = [context | emb[x]].
// ===========================================================================
__global__ void gru_kernel(const float* __restrict__ emb, const int* __restrict__ x,
                           const float* __restrict__ gru_k, const float* __restrict__ gru_b,
                           float* __restrict__ state) {
    __shared__ float xs[2][1280];
    int tid = threadIdx.x;
    int n = blockIdx.x * 128 + (tid & 127);
    int mi = tid >> 7;
    int m = blockIdx.y * 2 + mi;
    for (int i = tid; i < 2 * 1280; i += 256) {
        int mm = i / 1280, k = i % 1280;
        int gm = blockIdx.y * 2 + mm;
        xs[mm][k] = (k < 1024) ? g_context[gm * 1024 + k]
                               : emb[(size_t)x[gm] * 256 + (k - 1024)];
    }
    __syncthreads();
    float az = 0.f, ah = 0.f;
#pragma unroll 4
    for (int k = 0; k < 1280; k++) {
        float xv = xs[mi][k];
        az += xv * gru_k[(size_t)k * 3072 + n];
        ah += xv * gru_k[(size_t)k * 3072 + 2048 + n];
    }
    float z = 1.f / (1.f + expf(-(az + gru_b[n])));
    float hh = tanhf(ah + gru_b[2048 + n]);
    state[m * 1024 + n] = (1.f - z) * hh;
}

// ===========================================================================
// logits = state @ out_w + out_b   (M=64, N=32000, K=1024) — fp32 SIMT
// ===========================================================================
__global__ __launch_bounds__(256)
void logits_kernel(const float* __restrict__ state, const float* __restrict__ out_w,
                   const float* __restrict__ out_b, float* __restrict__ logits) {
    __shared__ float ss[64][64];
    int tid = threadIdx.x;
    int n = blockIdx.x * 128 + (tid & 31) * 4;
    int mg = tid >> 5;
    float acc[8][4] = {};
    for (int kt = 0; kt < 1024; kt += 64) {
        __syncthreads();
        for (int f = tid; f < 1024; f += 256) {
            int mm = f >> 4, kq = (f & 15) << 2;
            *(float4*)&ss[mm][kq] = *(const float4*)(state + mm * 1024 + kt + kq);
        }
        __syncthreads();
#pragma unroll 8
        for (int k = 0; k < 64; k++) {
            float4 w = *(const float4*)(out_w + (size_t)(kt + k) * 32000 + n);
#pragma unroll
            for (int mm = 0; mm < 8; mm++) {
                float s = ss[mg * 8 + mm][k];
                acc[mm][0] += s * w.x;
                acc[mm][1] += s * w.y;
                acc[mm][2] += s * w.z;
                acc[mm][3] += s * w.w;
            }
        }
    }
    float4 bv = *(const float4*)(out_b + n);
#pragma unroll
    for (int mm = 0; mm < 8; mm++) {
        float4 o;
        o.x = acc[mm][0] + bv.x;
        o.y = acc[mm][1] + bv.y;
        o.z = acc[mm][2] + bv.z;
        o.w = acc[mm][3] + bv.w;
        *(float4*)(logits + (size_t)(mg * 8 + mm) * 32000 + n) = o;
    }
}

// ===========================================================================
extern "C" void kernel_launch(void* const* d_in, const int* in_sizes, int n_in,
                              void* d_out, int out_size) {
    const int*   x      = (const int*)  d_in[0];
    const float* hidden = (const float*)d_in[1];
    const float* enc    = (const float*)d_in[2];
    const float* emb    = (const float*)d_in[3];
    const float* w1     = (const float*)d_in[4];
    const float* b1     = (const float*)d_in[5];
    const float* w2     = (const float*)d_in[6];
    const float* b2     = (const float*)d_in[7];
    const float* v_w    = (const float*)d_in[8];
    // d_in[9]  = v_b   : softmax-invariant uniform shift -> unused
    const float* gru_k  = (const float*)d_in[10];
    // d_in[11] = gru_rk: multiplied by h0 == 0 -> unused
    const float* gru_b  = (const float*)d_in[12];
    const float* out_w  = (const float*)d_in[13];
    const float* out_b  = (const float*)d_in[14];

    float* out    = (float*)d_out;
    float* logits = out;                          // (64, 32000)
    float* state  = out + (size_t)B_ * V_;        // (64, 1024)
    float* attn   = state + (size_t)B_ * U_;      // (64, 2048)

    cudaFuncSetAttribute(score_fp16, cudaFuncAttributeMaxDynamicSharedMemorySize, SC_SMEM);

    zero_kernel<<<512, 256>>>(b1, b2);
    transpose_w1h<<<dim3(32, 32), dim3(32, 8)>>>(w1);
    hidt_kernel<<<dim3(64, 4), 256>>>(hidden, w2);
    convert_enc<<<65536, 256>>>(enc);              // launch #4 (profiled this round)
    score_fp16<<<dim3(8, 1024), 256, SC_SMEM>>>(v_w);
    softmax_kernel<<<64, 256>>>(attn);
    context_kernel<<<dim3(64, 16), 256>>>(attn);
    gru_kernel<<<dim3(8, 32), 256>>>(emb, x, gru_k, gru_b, state);
    logits_kernel<<<250, 256>>>(state, out_w, out_b, logits);
}